// round 4
// baseline (speedup 1.0000x reference)
#include <cuda_runtime.h>

#define PI_F 3.14159265358979323846f

#define BN 32
#define NN 64
#define VOX (NN*NN*NN)      // 262144
#define NPC 66              // float2 row stride (swizzled plane)
#define PLANE_C2 (NN*NPC)   // 4224 float2 per plane

// swizzled cell index (float2 units): uniform-2 banks for every access pattern used
#define SWZ(row, col) ((row)*NPC + (((col) + 2*(row)) & 63))

// ---------------- scratch (static device globals; no allocation allowed) ----------------
__device__ float2 g_fw[BN*VOX];          // packed spectrum Z = FFT(X_t + i*Y); reused for Z*E
__device__ float  g_mats[BN*12];         // per-batch: rm[9], c[3]

// ---------------- complex helpers ----------------
struct C2 { float re, im; };
__device__ __forceinline__ C2 cadd(C2 a, C2 b){ return C2{a.re+b.re, a.im+b.im}; }
__device__ __forceinline__ C2 csub(C2 a, C2 b){ return C2{a.re-b.re, a.im-b.im}; }
__device__ __forceinline__ C2 cmulc(C2 a, float br, float bi){ return C2{a.re*br - a.im*bi, a.re*bi + a.im*br}; }
template<int S>
__device__ __forceinline__ C2 crot(C2 x){   // multiply by (0, S)
    return (S == -1) ? C2{x.im, -x.re} : C2{-x.im, x.re};
}

// 8-point DFT, natural order in/out, sign S (-1 fwd, +1 inv)
template<int S>
__device__ __forceinline__ void fft8(C2 r[8]) {
    const float H = 0.70710678118654752440f;
    C2 a0=cadd(r[0],r[4]), a1=cadd(r[1],r[5]), a2=cadd(r[2],r[6]), a3=cadd(r[3],r[7]);
    C2 s0=csub(r[0],r[4]), s1=csub(r[1],r[5]), s2=csub(r[2],r[6]), s3=csub(r[3],r[7]);
    C2 b0=s0;
    C2 b1=cmulc(s1,  H, (float)S*H);
    C2 b2=crot<S>(s2);
    C2 b3=cmulc(s3, -H, (float)S*H);
    C2 c0=cadd(a0,a2), c1=cadd(a1,a3), d0=csub(a0,a2), d1=crot<S>(csub(a1,a3));
    C2 e0=cadd(b0,b2), e1=cadd(b1,b3), f0=csub(b0,b2), f1=crot<S>(csub(b1,b3));
    r[0]=cadd(c0,c1); r[4]=csub(c0,c1);
    r[2]=cadd(d0,d1); r[6]=csub(d0,d1);
    r[1]=cadd(e0,e1); r[5]=csub(e0,e1);
    r[3]=cadd(f0,f1); r[7]=csub(f0,f1);
}

// 64-pt FFT in registers: input r[a] = x[8a+t], output r[c] = X[8c+t].
// Transpose staged through column `col` of float2 plane T (cells (p,col), p=0..63).
template<int S>
__device__ __forceinline__ void fft64s(C2 r[8], float2* T, int col, int t) {
    fft8<S>(r);
#pragma unroll
    for (int d=1;d<8;d++){
        float ang = (float)S * (6.28318530717958647692f/64.f) * (float)(t*d);
        float sn, cs; __sincosf(ang, &sn, &cs);
        r[d] = cmulc(r[d], cs, sn);
    }
    __syncwarp();
#pragma unroll
    for (int d=0;d<8;d++){
        int p = 8*d + ((d+t)&7);
        T[SWZ(p, col)] = make_float2(r[d].re, r[d].im);
    }
    __syncwarp();
#pragma unroll
    for (int b=0;b<8;b++){
        int p = 8*t + ((b+t)&7);
        float2 v = T[SWZ(p, col)];
        r[b] = C2{v.x, v.y};
    }
    __syncwarp();
    fft8<S>(r);
}

// ---------------- per-batch affine parameters ----------------
__global__ void mats_kernel(const float* __restrict__ theta) {
    int b = threadIdx.x;
    if (b >= BN) return;
    float t0=theta[b*6+0], t1=theta[b*6+1], t2=theta[b*6+2];
    float t3=theta[b*6+3], t4=theta[b*6+4], t5=theta[b*6+5];
    float phi = t0*2.f*PI_F - PI_F;
    float th  = t1*2.f*PI_F - PI_F;
    float psi = t2*2.f*PI_F - PI_F;
    float cf=cosf(phi), sf=sinf(phi), ct=cosf(th), st=sinf(th), cp=cosf(psi), sp=sinf(psi);
    float r00 =  cf*ct*cp - sf*sp;
    float r01 =  sf*ct*cp + cf*sp;
    float r02 = -st*cp;
    float r10 = -cf*ct*sp - sf*cp;
    float r11 = -sf*ct*sp + cf*cp;
    float r12 =  st*sp;
    float r20 =  cf*st;
    float r21 =  sf*st;
    float r22 =  ct;
    const float s = 64.f/66.f;
    float l0 = (2.f*t3-1.f)*s, l1=(2.f*t4-1.f)*s, l2=(2.f*t5-1.f)*s;
    float* M = g_mats + b*12;
    M[0]=r00; M[1]=r01; M[2]=r02;
    M[3]=r10; M[4]=r11; M[5]=r12;
    M[6]=r20; M[7]=r21; M[8]=r22;
    M[9]  = -(r00*l0 + r01*l1 + r02*l2);
    M[10] = -(r10*l0 + r11*l1 + r12*l2);
    M[11] = -(r20*l0 + r21*l1 + r22*l2);
}

__device__ __forceinline__ void corner(float u, int hi, int& i0, int& i1, float& d) {
    float f = floorf(u);
    int ii = (int)f;
    i0 = min(max(ii, 0), hi);
    i1 = min(max(ii + 1, 0), hi);
    d = u - (float)i0;          // delta vs *clipped* lower corner (matches reference)
}

// ---------------- mask warp kernel: rotation only, 64 grid, clamp border ----------------
__global__ void warp_masks_kernel(const float* __restrict__ m1,
                                  const float* __restrict__ m2,
                                  float* __restrict__ o1, float* __restrict__ o2) {
    int idx = blockIdx.x*256 + threadIdx.x;
    int b = idx >> 18;
    int rem = idx & (VOX-1);
    int i = rem >> 12, j = (rem >> 6) & 63, k = rem & 63;
    const float* M = g_mats + b*12;
    float r00=M[0],r01=M[1],r02=M[2],r10=M[3],r11=M[4],r12=M[5],r20=M[6],r21=M[7],r22=M[8];
    int base = b << 18;

    float gx = -1.f + (float)i*(2.f/63.f);
    float gy = -1.f + (float)j*(2.f/63.f);
    float gz = -1.f + (float)k*(2.f/63.f);
    float sx = r00*gx + r01*gy + r02*gz;
    float sy = r10*gx + r11*gy + r12*gz;
    float sz = r20*gx + r21*gy + r22*gz;
    float ux = (sx+1.f)*31.5f, uy=(sy+1.f)*31.5f, uz=(sz+1.f)*31.5f;
    int x0,x1,y0,y1,z0,z1; float dx,dy,dz;
    corner(ux,63,x0,x1,dx); corner(uy,63,y0,y1,dy); corner(uz,63,z0,z1,dz);
    float wx0=1.f-dx, wy0=1.f-dy, wz0=1.f-dz;
    const float* p1 = m1 + base;
    const float* p2 = m2 + base;
    int i000=(x0<<12)+(y0<<6)+z0, i001=(x0<<12)+(y0<<6)+z1;
    int i010=(x0<<12)+(y1<<6)+z0, i011=(x0<<12)+(y1<<6)+z1;
    int i100=(x1<<12)+(y0<<6)+z0, i101=(x1<<12)+(y0<<6)+z1;
    int i110=(x1<<12)+(y1<<6)+z0, i111=(x1<<12)+(y1<<6)+z1;
    float w000=wx0*wy0*wz0, w001=wx0*wy0*dz, w010=wx0*dy*wz0, w011=wx0*dy*dz;
    float w100=dx*wy0*wz0,  w101=dx*wy0*dz,  w110=dx*dy*wz0,  w111=dx*dy*dz;
    float v1 = w000*p1[i000]+w001*p1[i001]+w010*p1[i010]+w011*p1[i011]
             + w100*p1[i100]+w101*p1[i101]+w110*p1[i110]+w111*p1[i111];
    float v2 = w000*p2[i000]+w001*p2[i001]+w010*p2[i010]+w011*p2[i011]
             + w100*p2[i100]+w101*p2[i101]+w110*p2[i110]+w111*p2[i111];
    o1[idx] = v1;
    o2[idx] = v2;
}

// ---------------- FFT kernel A: warp X inline, pack W = X_t + i*Y, fwd z then y ----------------
// smem: P (data plane) + T (transpose scratch)
__global__ void __launch_bounds__(512, 2) fftA_kernel(const float* __restrict__ X,
                                                      const float* __restrict__ Y) {
    extern __shared__ unsigned char smraw[];
    float2* P = (float2*)smraw;
    float2* T = P + PLANE_C2;
    int bx = blockIdx.x;                  // b*64 + x
    int b = bx >> 6, x = bx & 63;
    int tid = threadIdx.x;
    int g = tid>>3, t = tid&7;            // octet: row/line index g

    const float* M = g_mats + b*12;
    float r00=M[0],r01=M[1],r02=M[2],r10=M[3],r11=M[4],r12=M[5],r20=M[6],r21=M[7],r22=M[8];
    float c0=M[9],c1=M[10],c2=M[11];
    const float* Xb = X + ((size_t)b << 18);
    const float* Yb = Y + ((size_t)bx << 12);

    // padded-66 grid coords for this (x, y=g) line; z = 8a+t
    float gxc = -1.f + (float)(x+1)*(2.f/65.f);
    float gyc = -1.f + (float)(g+1)*(2.f/65.f);
    float bxs = r00*gxc + r01*gyc + c0;
    float bys = r10*gxc + r11*gyc + c1;
    float bzs = r20*gxc + r21*gyc + c2;

    C2 r[8];
#pragma unroll
    for (int a=0;a<8;a++){
        int z = 8*a + t;
        float gzc = -1.f + (float)(z+1)*(2.f/65.f);
        float sx = bxs + r02*gzc;
        float sy = bys + r12*gzc;
        float sz = bzs + r22*gzc;
        float ux=(sx+1.f)*32.5f, uy=(sy+1.f)*32.5f, uz=(sz+1.f)*32.5f;
        int x0,x1,y0,y1,z0,z1; float dx,dy,dz;
        corner(ux,65,x0,x1,dx); corner(uy,65,y0,y1,dy); corner(uz,65,z0,z1,dz);
        float wx0=1.f-dx, wy0=1.f-dy, wz0=1.f-dz;
        auto fetch = [&](int p,int q,int rr)->float{
            if ((unsigned)(p-1)<64u && (unsigned)(q-1)<64u && (unsigned)(rr-1)<64u)
                return Xb[((p-1)<<12) + ((q-1)<<6) + (rr-1)];
            return 0.f;
        };
        float v = wx0*wy0*wz0*fetch(x0,y0,z0) + wx0*wy0*dz*fetch(x0,y0,z1)
                + wx0*dy*wz0*fetch(x0,y1,z0)  + wx0*dy*dz*fetch(x0,y1,z1)
                + dx*wy0*wz0*fetch(x1,y0,z0)  + dx*wy0*dz*fetch(x1,y0,z1)
                + dx*dy*wz0*fetch(x1,y1,z0)   + dx*dy*dz*fetch(x1,y1,z1);
        float yv = Yb[(g<<6) + z];
        r[a] = C2{v, yv};                 // W = X_t + i*Y
    }

    // forward FFT along z; store results in plane row y=g (col = kz)
    fft64s<-1>(r, T, g, t);
#pragma unroll
    for (int c=0;c<8;c++) P[SWZ(g, 8*c+t)] = make_float2(r[c].re, r[c].im);
    __syncthreads();

    // forward FFT along y: line = column kz=g
#pragma unroll
    for (int a=0;a<8;a++){ float2 v = P[SWZ(8*a+t, g)]; r[a] = C2{v.x, v.y}; }
    fft64s<-1>(r, T, g, t);
#pragma unroll
    for (int c=0;c<8;c++) P[SWZ(8*c+t, g)] = make_float2(r[c].re, r[c].im);
    __syncthreads();

    // dense out (float4 = 2 cells)
    float4* dst = (float4*)(g_fw + ((size_t)bx << 12));
#pragma unroll
    for (int i=0;i<4;i++){
        int p2 = tid + i*512;             // float4 index: 2048 per plane
        int idx = p2*2;
        int row = idx>>6, col = idx&63;
        dst[p2] = *(const float4*)&P[SWZ(row,col)];
    }
}

// ---------------- FFT kernel B: fwd-x, pointwise Z*E (reg-resident), inv-x ----------------
// E[k] = (0.5/64^3)*((w1[k]+w1[-k]) - i*(w2[k]+w2[-k])), w[k]=M_t[(k+32)%64 per axis]
__global__ void __launch_bounds__(512, 2) fftB_kernel(const float* __restrict__ m1t,
                                                      const float* __restrict__ m2t) {
    extern __shared__ unsigned char smraw[];
    float2* P = (float2*)smraw;
    float2* E = P + PLANE_C2;
    float2* T = E + PLANE_C2;
    int bid = blockIdx.x;                 // b*64 + ky
    int b = bid >> 6, y = bid & 63;
    int tid = threadIdx.x;
    int g = tid>>3, t = tid&7;

    size_t base = ((size_t)b << 18);
    size_t ybase = base + ((size_t)y << 6);
    int ys  = y ^ 32;
    int ys2 = (32 - y) & 63;
    const float SC = 1.f/262144.f;

    const float2* src = g_fw + ybase;
#pragma unroll
    for (int i=0;i<8;i++){
        int idx = tid + i*512;
        int kx = idx>>6, kz = idx&63;
        P[SWZ(kx,kz)] = src[((size_t)kx<<12) + kz];
        int xs  = kx ^ 32,       zs  = kz ^ 32;
        int xs2 = (32-kx) & 63,  zs2 = (32-kz) & 63;
        size_t o1 = base + ((size_t)xs <<12) + (ys <<6) + zs;
        size_t o2 = base + ((size_t)xs2<<12) + (ys2<<6) + zs2;
        float er =  0.5f*SC*(m1t[o1] + m1t[o2]);
        float ei = -0.5f*SC*(m2t[o1] + m2t[o2]);
        E[SWZ(kx,kz)] = make_float2(er, ei);
    }
    __syncthreads();

    // line along x at fixed kz=g: entirely in registers
    C2 r[8];
#pragma unroll
    for (int a=0;a<8;a++){ float2 v = P[SWZ(8*a+t, g)]; r[a] = C2{v.x, v.y}; }
    fft64s<-1>(r, T, g, t);
#pragma unroll
    for (int c=0;c<8;c++){
        float2 e = E[SWZ(8*c+t, g)];
        r[c] = cmulc(r[c], e.x, e.y);
    }
    fft64s<1>(r, T, g, t);
#pragma unroll
    for (int c=0;c<8;c++) P[SWZ(8*c+t, g)] = make_float2(r[c].re, r[c].im);
    __syncthreads();

#pragma unroll
    for (int i=0;i<8;i++){
        int idx = tid + i*512;
        int xx = idx>>6, kz = idx&63;
        g_fw[ybase + ((size_t)xx<<12) + kz] = P[SWZ(xx,kz)];
    }
}

// ---------------- FFT kernel C: inverse z then y, real part ----------------
__global__ void __launch_bounds__(512, 2) fftC_kernel(float* __restrict__ out0) {
    extern __shared__ unsigned char smraw[];
    float2* P = (float2*)smraw;
    float2* T = P + PLANE_C2;
    int bx = blockIdx.x;
    int tid = threadIdx.x;
    int g = tid>>3, t = tid&7;

    const float2* src = g_fw + ((size_t)bx << 12);
    C2 r[8];
#pragma unroll
    for (int a=0;a<8;a++){
        float2 v = src[(g<<6) + 8*a + t];
        r[a] = C2{v.x, v.y};
    }
    fft64s<1>(r, T, g, t);               // inverse z (row y=g)
#pragma unroll
    for (int c=0;c<8;c++) P[SWZ(g, 8*c+t)] = make_float2(r[c].re, r[c].im);
    __syncthreads();

#pragma unroll
    for (int a=0;a<8;a++){ float2 v = P[SWZ(8*a+t, g)]; r[a] = C2{v.x, v.y}; }
    fft64s<1>(r, T, g, t);               // inverse y (column z=g)
#pragma unroll
    for (int c=0;c<8;c++) P[SWZ(8*c+t, g)] = make_float2(r[c].re, r[c].im);
    __syncthreads();

    // write real part: 2 cells -> float2 store
    float2* dst = (float2*)(out0 + ((size_t)bx << 12));
#pragma unroll
    for (int i=0;i<4;i++){
        int p2 = tid + i*512;
        int idx = p2*2;
        int row = idx>>6, col = idx&63;
        float4 v = *(const float4*)&P[SWZ(row,col)];
        dst[p2] = make_float2(v.x, v.z);
    }
}

// ---------------- launcher ----------------
extern "C" void kernel_launch(void* const* d_in, const int* in_sizes, int n_in,
                              void* d_out, int out_size) {
    const float* X  = (const float*)d_in[0];
    const float* Y  = (const float*)d_in[1];
    const float* m1 = (const float*)d_in[2];
    const float* m2 = (const float*)d_in[3];
    const float* th = (const float*)d_in[4];
    float* out0 = (float*)d_out;                 // real(ifft(...))
    float* out1 = out0 + (size_t)BN*VOX;         // M1_t
    float* out2 = out1 + (size_t)BN*VOX;         // M2_t

    const int SMA = 2*PLANE_C2*8;   // 67,584 B
    const int SMB = 3*PLANE_C2*8;   // 101,376 B
    cudaFuncSetAttribute(fftA_kernel, cudaFuncAttributeMaxDynamicSharedMemorySize, SMA);
    cudaFuncSetAttribute(fftB_kernel, cudaFuncAttributeMaxDynamicSharedMemorySize, SMB);
    cudaFuncSetAttribute(fftC_kernel, cudaFuncAttributeMaxDynamicSharedMemorySize, SMA);

    mats_kernel<<<1, 32>>>(th);
    warp_masks_kernel<<<(BN*VOX)/256, 256>>>(m1, m2, out1, out2);
    fftA_kernel<<<BN*NN, 512, SMA>>>(X, Y);        // warp X + pack + z,y FFT -> g_fw
    fftB_kernel<<<BN*NN, 512, SMB>>>(out1, out2);  // x FFT + Z*E + x IFFT (regs)
    fftC_kernel<<<BN*NN, 512, SMA>>>(out0);        // z,y IFFT + real
}

// round 5
// speedup vs baseline: 1.0641x; 1.0641x over previous
#include <cuda_runtime.h>

#define PI_F 3.14159265358979323846f

#define BN 32
#define NN 64
#define VOX (NN*NN*NN)      // 262144
#define NP 72               // padded plane line stride (floats)
#define PLANE_F (NN*NP)     // 4608 floats per plane array

// ---------------- scratch (static device globals; no allocation allowed) ----------------
__device__ float2 g_fw[BN*VOX];          // packed spectrum Z = FFT(X_t + i*Y); reused for Z*E
__device__ float  g_mats[BN*12];         // per-batch: rm[9], c[3]

// ---------------- complex helpers ----------------
struct C2 { float re, im; };
__device__ __forceinline__ C2 cadd(C2 a, C2 b){ return C2{a.re+b.re, a.im+b.im}; }
__device__ __forceinline__ C2 csub(C2 a, C2 b){ return C2{a.re-b.re, a.im-b.im}; }
__device__ __forceinline__ C2 cmulc(C2 a, float br, float bi){ return C2{a.re*br - a.im*bi, a.re*bi + a.im*br}; }
template<int S>
__device__ __forceinline__ C2 crot(C2 x){   // multiply by (0, S)
    return (S == -1) ? C2{x.im, -x.re} : C2{-x.im, x.re};
}

// 8-point DFT, natural order in/out, sign S (-1 fwd, +1 inv)
template<int S>
__device__ __forceinline__ void fft8(C2 r[8]) {
    const float H = 0.70710678118654752440f;
    C2 a0=cadd(r[0],r[4]), a1=cadd(r[1],r[5]), a2=cadd(r[2],r[6]), a3=cadd(r[3],r[7]);
    C2 s0=csub(r[0],r[4]), s1=csub(r[1],r[5]), s2=csub(r[2],r[6]), s3=csub(r[3],r[7]);
    C2 b0=s0;
    C2 b1=cmulc(s1,  H, (float)S*H);
    C2 b2=crot<S>(s2);
    C2 b3=cmulc(s3, -H, (float)S*H);
    C2 c0=cadd(a0,a2), c1=cadd(a1,a3), d0=csub(a0,a2), d1=crot<S>(csub(a1,a3));
    C2 e0=cadd(b0,b2), e1=cadd(b1,b3), f0=csub(b0,b2), f1=crot<S>(csub(b1,b3));
    r[0]=cadd(c0,c1); r[4]=csub(c0,c1);
    r[2]=cadd(d0,d1); r[6]=csub(d0,d1);
    r[1]=cadd(e0,e1); r[5]=csub(e0,e1);
    r[3]=cadd(f0,f1); r[7]=csub(f0,f1);
}

// Core of the 64-pt FFT: input r[a] = x[8a+t], output r[c] = X[8c+t].
// temp (tre/tim, per-group 72-float regions) used for the 8x8 transpose.
template<int S>
__device__ __forceinline__ void fft64_regs(C2 r[8], float* tre, float* tim, int t) {
    fft8<S>(r);
#pragma unroll
    for (int d=1;d<8;d++){
        float ang = (float)S * (6.28318530717958647692f/64.f) * (float)(t*d);
        float sn, cs; __sincosf(ang, &sn, &cs);
        r[d] = cmulc(r[d], cs, sn);
    }
    __syncwarp();
#pragma unroll
    for (int d=0;d<8;d++){ int p = 8*d + ((d+t)&7); tre[p]=r[d].re; tim[p]=r[d].im; }
    __syncwarp();
#pragma unroll
    for (int b=0;b<8;b++){ int p = 8*t + ((b+t)&7); r[b]=C2{tre[p],tim[p]}; }
    __syncwarp();
    fft8<S>(r);
}

// 64-point FFT on a shared-memory line (element i at re[i*stride], im[i*stride]).
template<int S>
__device__ __forceinline__ void fft64g(float* re, float* im, int stride,
                                       float* tre, float* tim, int t) {
    C2 r[8];
#pragma unroll
    for (int a=0;a<8;a++){ int p=(8*a+t)*stride; r[a]=C2{re[p],im[p]}; }
    fft64_regs<S>(r, tre, tim, t);
#pragma unroll
    for (int c=0;c<8;c++){ int p=(8*c+t)*stride; re[p]=r[c].re; im[p]=r[c].im; }
}

// ---------------- per-batch affine parameters ----------------
__global__ void mats_kernel(const float* __restrict__ theta) {
    int b = threadIdx.x;
    if (b >= BN) return;
    float t0=theta[b*6+0], t1=theta[b*6+1], t2=theta[b*6+2];
    float t3=theta[b*6+3], t4=theta[b*6+4], t5=theta[b*6+5];
    float phi = t0*2.f*PI_F - PI_F;
    float th  = t1*2.f*PI_F - PI_F;
    float psi = t2*2.f*PI_F - PI_F;
    float cf=cosf(phi), sf=sinf(phi), ct=cosf(th), st=sinf(th), cp=cosf(psi), sp=sinf(psi);
    float r00 =  cf*ct*cp - sf*sp;
    float r01 =  sf*ct*cp + cf*sp;
    float r02 = -st*cp;
    float r10 = -cf*ct*sp - sf*cp;
    float r11 = -sf*ct*sp + cf*cp;
    float r12 =  st*sp;
    float r20 =  cf*st;
    float r21 =  sf*st;
    float r22 =  ct;
    const float s = 64.f/66.f;
    float l0 = (2.f*t3-1.f)*s, l1=(2.f*t4-1.f)*s, l2=(2.f*t5-1.f)*s;
    float* M = g_mats + b*12;
    M[0]=r00; M[1]=r01; M[2]=r02;
    M[3]=r10; M[4]=r11; M[5]=r12;
    M[6]=r20; M[7]=r21; M[8]=r22;
    M[9]  = -(r00*l0 + r01*l1 + r02*l2);
    M[10] = -(r10*l0 + r11*l1 + r12*l2);
    M[11] = -(r20*l0 + r21*l1 + r22*l2);
}

__device__ __forceinline__ void corner(float u, int hi, int& i0, int& i1, float& d) {
    float f = floorf(u);
    int ii = (int)f;
    i0 = min(max(ii, 0), hi);
    i1 = min(max(ii + 1, 0), hi);
    d = u - (float)i0;          // delta vs *clipped* lower corner (matches reference)
}

// ---------------- mask warp kernel: rotation only, 64 grid, clamp border ----------------
__global__ void warp_masks_kernel(const float* __restrict__ m1,
                                  const float* __restrict__ m2,
                                  float* __restrict__ o1, float* __restrict__ o2) {
    int idx = blockIdx.x*256 + threadIdx.x;
    int b = idx >> 18;
    int rem = idx & (VOX-1);
    int i = rem >> 12, j = (rem >> 6) & 63, k = rem & 63;
    const float* M = g_mats + b*12;
    float r00=M[0],r01=M[1],r02=M[2],r10=M[3],r11=M[4],r12=M[5],r20=M[6],r21=M[7],r22=M[8];
    int base = b << 18;

    float gx = -1.f + (float)i*(2.f/63.f);
    float gy = -1.f + (float)j*(2.f/63.f);
    float gz = -1.f + (float)k*(2.f/63.f);
    float sx = r00*gx + r01*gy + r02*gz;
    float sy = r10*gx + r11*gy + r12*gz;
    float sz = r20*gx + r21*gy + r22*gz;
    float ux = (sx+1.f)*31.5f, uy=(sy+1.f)*31.5f, uz=(sz+1.f)*31.5f;
    int x0,x1,y0,y1,z0,z1; float dx,dy,dz;
    corner(ux,63,x0,x1,dx); corner(uy,63,y0,y1,dy); corner(uz,63,z0,z1,dz);
    float wx0=1.f-dx, wy0=1.f-dy, wz0=1.f-dz;
    const float* p1 = m1 + base;
    const float* p2 = m2 + base;
    int i000=(x0<<12)+(y0<<6)+z0, i001=(x0<<12)+(y0<<6)+z1;
    int i010=(x0<<12)+(y1<<6)+z0, i011=(x0<<12)+(y1<<6)+z1;
    int i100=(x1<<12)+(y0<<6)+z0, i101=(x1<<12)+(y0<<6)+z1;
    int i110=(x1<<12)+(y1<<6)+z0, i111=(x1<<12)+(y1<<6)+z1;
    float w000=wx0*wy0*wz0, w001=wx0*wy0*dz, w010=wx0*dy*wz0, w011=wx0*dy*dz;
    float w100=dx*wy0*wz0,  w101=dx*wy0*dz,  w110=dx*dy*wz0,  w111=dx*dy*dz;
    float v1 = w000*p1[i000]+w001*p1[i001]+w010*p1[i010]+w011*p1[i011]
             + w100*p1[i100]+w101*p1[i101]+w110*p1[i110]+w111*p1[i111];
    float v2 = w000*p2[i000]+w001*p2[i001]+w010*p2[i010]+w011*p2[i011]
             + w100*p2[i100]+w101*p2[i101]+w110*p2[i110]+w111*p2[i111];
    o1[idx] = v1;
    o2[idx] = v2;
}

// ---------------- FFT kernel A: warp X inline, pack W = X_t + i*Y, forward z then y ----------------
__global__ void __launch_bounds__(512, 2) fftA_kernel(const float* __restrict__ X,
                                                      const float* __restrict__ Y) {
    extern __shared__ float sm[];
    float* s_re = sm;
    float* s_im = sm +   PLANE_F;
    float* t_re = sm + 2*PLANE_F;
    float* t_im = sm + 3*PLANE_F;
    int bx = blockIdx.x;                  // b*64 + x
    int b = bx >> 6, x = bx & 63;
    int tid = threadIdx.x;
    int g = tid>>3, t = tid&7;            // line y=g, octet t

    const float* M = g_mats + b*12;
    float r00=M[0],r01=M[1],r02=M[2],r10=M[3],r11=M[4],r12=M[5],r20=M[6],r21=M[7],r22=M[8];
    float c0=M[9],c1=M[10],c2=M[11];
    const float* Xb = X + ((size_t)b << 18);
    const float* Yb = Y + ((size_t)bx << 12);   // plane (b,x) of Y, contiguous

    // padded-66 grid coords for this (x, y=g) line; z = 8a+t
    float gxc = -1.f + (float)(x+1)*(2.f/65.f);
    float gyc = -1.f + (float)(g+1)*(2.f/65.f);
    float bxs = r00*gxc + r01*gyc + c0;
    float bys = r10*gxc + r11*gyc + c1;
    float bzs = r20*gxc + r21*gyc + c2;

    C2 r[8];
#pragma unroll
    for (int a=0;a<8;a++){
        int z = 8*a + t;
        float gzc = -1.f + (float)(z+1)*(2.f/65.f);
        float sx = bxs + r02*gzc;
        float sy = bys + r12*gzc;
        float sz = bzs + r22*gzc;
        float ux=(sx+1.f)*32.5f, uy=(sy+1.f)*32.5f, uz=(sz+1.f)*32.5f;
        int x0,x1,y0,y1,z0,z1; float dx,dy,dz;
        corner(ux,65,x0,x1,dx); corner(uy,65,y0,y1,dy); corner(uz,65,z0,z1,dz);
        float wx0=1.f-dx, wy0=1.f-dy, wz0=1.f-dz;
        auto fetch = [&](int p,int q,int rr)->float{
            if ((unsigned)(p-1)<64u && (unsigned)(q-1)<64u && (unsigned)(rr-1)<64u)
                return Xb[((p-1)<<12) + ((q-1)<<6) + (rr-1)];
            return 0.f;
        };
        float v = wx0*wy0*wz0*fetch(x0,y0,z0) + wx0*wy0*dz*fetch(x0,y0,z1)
                + wx0*dy*wz0*fetch(x0,y1,z0)  + wx0*dy*dz*fetch(x0,y1,z1)
                + dx*wy0*wz0*fetch(x1,y0,z0)  + dx*wy0*dz*fetch(x1,y0,z1)
                + dx*dy*wz0*fetch(x1,y1,z0)   + dx*dy*dz*fetch(x1,y1,z1);
        float yv = Yb[(g<<6) + z];
        r[a] = C2{v, yv};                 // W = X_t + i*Y
    }

    // forward FFT along z (in registers; transpose via group temp)
    fft64_regs<-1>(r, t_re + g*NP, t_im + g*NP, t);
#pragma unroll
    for (int c=0;c<8;c++){ int p = g*NP + (8*c+t); s_re[p]=r[c].re; s_im[p]=r[c].im; }
    __syncthreads();

    // forward FFT along y (strided column kz = g)
    fft64g<-1>(s_re + g, s_im + g, NP, t_re + g*NP, t_im + g*NP, t);
    __syncthreads();

    float2* dst = g_fw + ((size_t)bx << 12);
#pragma unroll
    for (int i=0;i<8;i++){
        int idx = tid + i*512;
        int y = idx>>6, z = idx&63;
        dst[idx] = make_float2(s_re[y*NP+z], s_im[y*NP+z]);
    }
}

// ---------------- FFT kernel B: fwd-x, pointwise Z*E (symmetrized masks), inv-x ----------------
// out = real(ifft3(Z*E)),  E[k] = 0.5*((w1[k]+w1[-k]) - i*(w2[k]+w2[-k])),
// w_i[k] = M_i_t[(k+32) mod 64 per axis]  (fftshift roll folded in).
// Latency-hiding layout: all global loads hoisted to the top (batched MLP),
// E staged to smem once; the per-line fwd-FFT -> multiply -> inv-FFT runs in registers.
__global__ void __launch_bounds__(512, 2) fftB_kernel(const float* __restrict__ m1t,
                                                      const float* __restrict__ m2t) {
    extern __shared__ float sm[];
    float* s_re = sm;
    float* s_im = sm +   PLANE_F;
    float* e_re = sm + 2*PLANE_F;
    float* e_im = sm + 3*PLANE_F;
    float* t_re = sm + 4*PLANE_F;
    float* t_im = sm + 5*PLANE_F;
    int bid = blockIdx.x;                 // b*64 + ky
    int b = bid >> 6, y = bid & 63;
    int tid = threadIdx.x;
    int g = tid>>3, t = tid&7;

    size_t base = ((size_t)b << 18);
    size_t ybase = base + ((size_t)y << 6);
    int ys  = y ^ 32;
    int ys2 = (32 - y) & 63;

    // ---- phase 1: batched global loads (spectrum + masks), stage to smem ----
    {
        float2 zv[8];
#pragma unroll
        for (int i=0;i<8;i++){
            int idx = tid + i*512;
            int kx = idx>>6, kz = idx&63;
            zv[i] = g_fw[ybase + ((size_t)kx<<12) + kz];
        }
#pragma unroll
        for (int i=0;i<8;i++){
            int idx = tid + i*512;
            int kx = idx>>6, kz = idx&63;
            s_re[kx*NP+kz] = zv[i].x;
            s_im[kx*NP+kz] = zv[i].y;
        }
    }
#pragma unroll
    for (int h=0;h<2;h++){
        float a1[4], a2[4], b1[4], b2[4];
#pragma unroll
        for (int i=0;i<4;i++){
            int idx = tid + (h*4+i)*512;
            int kx = idx>>6, kz = idx&63;
            int xs  = kx ^ 32,       zs  = kz ^ 32;
            int xs2 = (32-kx) & 63,  zs2 = (32-kz) & 63;
            size_t o1 = base + ((size_t)xs <<12) + (ys <<6) + zs;
            size_t o2 = base + ((size_t)xs2<<12) + (ys2<<6) + zs2;
            a1[i] = m1t[o1]; b1[i] = m1t[o2];
            a2[i] = m2t[o1]; b2[i] = m2t[o2];
        }
#pragma unroll
        for (int i=0;i<4;i++){
            int idx = tid + (h*4+i)*512;
            int kx = idx>>6, kz = idx&63;
            e_re[kx*NP+kz] =  0.5f*(a1[i] + b1[i]);
            e_im[kx*NP+kz] = -0.5f*(a2[i] + b2[i]);
        }
    }
    __syncthreads();

    // ---- phase 2: register-resident line pipeline along x (line kz = g) ----
    C2 r[8];
#pragma unroll
    for (int a=0;a<8;a++){
        int p = (8*a+t)*NP + g;
        r[a] = C2{s_re[p], s_im[p]};
    }
    fft64_regs<-1>(r, t_re + g*NP, t_im + g*NP, t);   // forward x
#pragma unroll
    for (int c=0;c<8;c++){
        int p = (8*c+t)*NP + g;
        r[c] = cmulc(r[c], e_re[p], e_im[p]);
    }
    fft64_regs<1>(r, t_re + g*NP, t_im + g*NP, t);    // inverse x
#pragma unroll
    for (int c=0;c<8;c++){
        int p = (8*c+t)*NP + g;
        s_re[p] = r[c].re; s_im[p] = r[c].im;
    }
    __syncthreads();

    // ---- phase 3: coalesced store-back ----
#pragma unroll
    for (int i=0;i<8;i++){
        int idx = tid + i*512;
        int xx = idx>>6, kz = idx&63;
        g_fw[ybase + ((size_t)xx<<12) + kz] = make_float2(s_re[xx*NP+kz], s_im[xx*NP+kz]);
    }
}

// ---------------- FFT kernel C: inverse z then y, scale, real part ----------------
__global__ void __launch_bounds__(512, 2) fftC_kernel(float* __restrict__ out0) {
    extern __shared__ float sm[];
    float* s_re = sm;
    float* s_im = sm +   PLANE_F;
    float* t_re = sm + 2*PLANE_F;
    float* t_im = sm + 3*PLANE_F;
    int bx = blockIdx.x;
    int tid = threadIdx.x;
    int g = tid>>3, t = tid&7;

    const float2* src = g_fw + ((size_t)bx << 12);
    C2 r[8];
#pragma unroll
    for (int a=0;a<8;a++){
        float2 v = src[(g<<6) + 8*a + t];
        r[a] = C2{v.x, v.y};
    }
    fft64_regs<1>(r, t_re + g*NP, t_im + g*NP, t);   // inverse z (line y=g)
#pragma unroll
    for (int c=0;c<8;c++){ int p = g*NP + (8*c+t); s_re[p]=r[c].re; s_im[p]=r[c].im; }
    __syncthreads();

    fft64g<1>(s_re + g, s_im + g, NP, t_re + g*NP, t_im + g*NP, t);   // inverse y
    __syncthreads();

    const float sc = 1.f/262144.f;   // 1/64^3
#pragma unroll
    for (int i=0;i<8;i++){
        int idx = tid + i*512;
        int y = idx>>6, z = idx&63;
        out0[((size_t)bx<<12) + idx] = s_re[y*NP+z] * sc;
    }
}

// ---------------- launcher ----------------
extern "C" void kernel_launch(void* const* d_in, const int* in_sizes, int n_in,
                              void* d_out, int out_size) {
    const float* X  = (const float*)d_in[0];
    const float* Y  = (const float*)d_in[1];
    const float* m1 = (const float*)d_in[2];
    const float* m2 = (const float*)d_in[3];
    const float* th = (const float*)d_in[4];
    float* out0 = (float*)d_out;                 // real(ifft(...))
    float* out1 = out0 + (size_t)BN*VOX;         // M1_t
    float* out2 = out1 + (size_t)BN*VOX;         // M2_t

    const int SMA = 4*PLANE_F*4;   // 73,728 B
    const int SMB = 6*PLANE_F*4;   // 110,592 B
    cudaFuncSetAttribute(fftA_kernel, cudaFuncAttributeMaxDynamicSharedMemorySize, SMA);
    cudaFuncSetAttribute(fftB_kernel, cudaFuncAttributeMaxDynamicSharedMemorySize, SMB);
    cudaFuncSetAttribute(fftC_kernel, cudaFuncAttributeMaxDynamicSharedMemorySize, SMA);

    mats_kernel<<<1, 32>>>(th);
    warp_masks_kernel<<<(BN*VOX)/256, 256>>>(m1, m2, out1, out2);
    fftA_kernel<<<BN*NN, 512, SMA>>>(X, Y);        // warp X + pack + z,y FFT -> g_fw
    fftB_kernel<<<BN*NN, 512, SMB>>>(out1, out2);  // x FFT + Z*E + x IFFT (hoisted loads, reg pipeline)
    fftC_kernel<<<BN*NN, 512, SMA>>>(out0);        // z,y IFFT + scale + real
}